// round 10
// baseline (speedup 1.0000x reference)
#include <cuda_runtime.h>
#include <cuda_fp16.h>
#include <cstdint>

// Problem constants
#define BB 8192
#define DD 300
#define HH 512
#define WW 8
#define KC 832          // combined K: 320 (x, padded from 300) + 512 (h0)
#define KXP 320         // padded x-only K

// ---------------- scratch (no allocations allowed) ----------------
__device__ __half g_xh[(size_t)BB * KC];         // packed fp16 [x | h0]
__device__ __half g_ac16[(size_t)BB * WW * HH];  // fp16 allc
__device__ __half g_wt16[1703936];               // fp16 weights [N,Kpad]
#define G_I  0
#define G_G  425984
#define G_O  851968
#define G_LX 1277952
#define G_LC 1441792
__device__ float g_pre[(size_t)4 * BB * HH];     // ipre, gpre, opre, lxproj
__device__ float g_bsum[3 * HH];

// ---------------- helpers ----------------
__device__ __forceinline__ uint32_t smem_u32(const void* p) {
    uint32_t a;
    asm("{ .reg .u64 t; cvta.to.shared.u64 t, %1; cvt.u32.u64 %0, t; }"
        : "=r"(a) : "l"(p));
    return a;
}
__device__ __forceinline__ void cp16(uint32_t dst, const void* src, bool pred) {
    asm volatile("cp.async.cg.shared.global [%0], [%1], 16, %2;"
                 :: "r"(dst), "l"(src), "r"(pred ? 16 : 0));
}
#define CP_COMMIT() asm volatile("cp.async.commit_group;")
#define CP_WAIT(n)  asm volatile("cp.async.wait_group %0;" :: "n"(n))
#define LDSM_X4(r0, r1, r2, r3, addr) \
    asm volatile("ldmatrix.sync.aligned.m8n8.x4.shared.b16 {%0,%1,%2,%3}, [%4];" \
                 : "=r"(r0), "=r"(r1), "=r"(r2), "=r"(r3) : "r"(addr))

// ---------------- conversion kernels ----------------
__global__ void __launch_bounds__(256)
conv_pack(const float* __restrict__ src, __half* __restrict__ dst,
          int f4_per_row, int src_stride, int dst_stride, int dst_off, int n4)
{
    int i = blockIdx.x * blockDim.x + threadIdx.x;
    if (i >= n4) return;
    int row = i / f4_per_row, c = i - row * f4_per_row;
    float4 v = *reinterpret_cast<const float4*>(src + (size_t)row * src_stride + c * 4);
    __half2 h01 = __floats2half2_rn(v.x, v.y);
    __half2 h23 = __floats2half2_rn(v.z, v.w);
    uint2 o = make_uint2(*reinterpret_cast<uint32_t*>(&h01),
                         *reinterpret_cast<uint32_t*>(&h23));
    *reinterpret_cast<uint2*>(dst + (size_t)row * dst_stride + dst_off + c * 4) = o;
}

struct TSet { const float* s[8]; int K[8]; int dst[8]; int strideW[8]; };

__global__ void __launch_bounds__(256)
prep_w(TSet ts, __half* __restrict__ wt)
{
    int z = blockIdx.z;
    int K = ts.K[z];
    int k0 = blockIdx.y * 32;
    if (k0 >= K) return;
    int n0 = blockIdx.x * 32;

    __shared__ float s[32][33];
    int tx = threadIdx.x & 31, ty = threadIdx.x >> 5;
#pragma unroll
    for (int i = 0; i < 4; i++) {
        int k = k0 + ty + 8 * i;
        s[ty + 8 * i][tx] = (k < K) ? ts.s[z][(size_t)k * HH + n0 + tx] : 0.f;
    }
    __syncthreads();
#pragma unroll
    for (int i = 0; i < 4; i++) {
        int n = n0 + ty + 8 * i;
        int kk = k0 + tx;
        if (kk < K)
            wt[(size_t)ts.dst[z] + (size_t)n * ts.strideW[z] + kk] =
                __float2half_rn(s[tx][ty + 8 * i]);
    }
}

__global__ void __launch_bounds__(256)
bias_sum(const float* a0, const float* b0, const float* a1, const float* b1,
         const float* a2, const float* b2, float* out)
{
    int i = blockIdx.x * blockDim.x + threadIdx.x;
    if (i >= HH) return;
    out[i]          = a0[i] + b0[i];
    out[HH + i]     = a1[i] + b1[i];
    out[2 * HH + i] = a2[i] + b2[i];
}

// ---------------- shared GEMM tiling constants ----------------
#define BKH 64
#define ROWB 144
#define TILE_B (128 * ROWB)
#define STAGE_B (2 * TILE_B)
#define SMEM_BYTES (2 * STAGE_B)   // 73728

// ---------------- fp16 GEMM: gates + lx (4 jobs) ----------------
struct Jobs4 {
    const __half* A[4];
    const __half* W[4];
    const float*  bias[4];
    float*        C[4];
    int           sA[4], sW[4], nk[4], start[4];
};

__global__ void __launch_bounds__(256)
gemm_fp16(Jobs4 jb)
{
    extern __shared__ __align__(16) char sm_[];

    const int bid = blockIdx.x;
    int j = 0;
#pragma unroll
    for (int t = 1; t < 4; t++) if (bid >= jb.start[t]) j = t;

    const __half* __restrict__ A    = jb.A[j];
    const __half* __restrict__ W    = jb.W[j];
    const float*  __restrict__ bias = jb.bias[j];
    float*        __restrict__ C    = jb.C[j];
    const int sA = jb.sA[j], sW = jb.sW[j], nk = jb.nk[j];

    const int local = bid - jb.start[j];
    const int row0 = (local >> 2) * 128;
    const int col0 = (local & 3) * 128;

    const int tid  = threadIdx.x;
    const int wid  = tid >> 5;
    const int lane = tid & 31;
    const int wrow = wid >> 1;
    const int wcol = wid & 1;
    const int g  = lane >> 2;
    const int c4 = lane & 3;
    const int lm_row = lane & 15;
    const int lm_col = (lane >> 4) * 16;

    float acc[2][8][4];
#pragma unroll
    for (int mt = 0; mt < 2; mt++)
#pragma unroll
        for (int nt = 0; nt < 8; nt++)
#pragma unroll
            for (int r = 0; r < 4; r++) acc[mt][nt][r] = 0.f;

    const uint32_t smb = smem_u32(sm_);

    auto load_stage = [&](int s, int kb) {
        uint32_t sAb = smb + s * STAGE_B;
        uint32_t sBb = sAb + TILE_B;
        int k0 = kb * BKH;
#pragma unroll
        for (int i = 0; i < 4; i++) {
            int id = tid + i * 256;
            int r = id >> 3, ch = id & 7;
            cp16(sAb + r * ROWB + ch * 16,
                 A + (size_t)(row0 + r) * sA + k0 + ch * 8, true);
        }
#pragma unroll
        for (int i = 0; i < 4; i++) {
            int id = tid + i * 256;
            int r = id >> 3, ch = id & 7;
            cp16(sBb + r * ROWB + ch * 16,
                 W + (size_t)(col0 + r) * sW + k0 + ch * 8, true);
        }
        CP_COMMIT();
    };

    load_stage(0, 0);

    for (int kb = 0; kb < nk; kb++) {
        if (kb + 1 < nk) { load_stage((kb + 1) & 1, kb + 1); CP_WAIT(1); }
        else             { CP_WAIT(0); }
        __syncthreads();

        const uint32_t As = smb + (kb & 1) * STAGE_B;
        const uint32_t Bs = As + TILE_B;

#pragma unroll
        for (int kk = 0; kk < 4; kk++) {
            uint32_t af[2][4], bf[8][2];
            const int kby = kk * 32 + lm_col;
#pragma unroll
            for (int mt = 0; mt < 2; mt++) {
                uint32_t ad = As + (wrow * 32 + mt * 16 + lm_row) * ROWB + kby;
                LDSM_X4(af[mt][0], af[mt][1], af[mt][2], af[mt][3], ad);
            }
#pragma unroll
            for (int ntp = 0; ntp < 4; ntp++) {
                uint32_t bd = Bs + (wcol * 64 + ntp * 16 + lm_row) * ROWB + kby;
                LDSM_X4(bf[2 * ntp][0], bf[2 * ntp + 1][0],
                        bf[2 * ntp][1], bf[2 * ntp + 1][1], bd);
            }
#pragma unroll
            for (int mt = 0; mt < 2; mt++)
#pragma unroll
                for (int nt = 0; nt < 8; nt++) {
                    asm volatile(
                        "mma.sync.aligned.m16n8k16.row.col.f32.f16.f16.f32 "
                        "{%0,%1,%2,%3}, {%4,%5,%6,%7}, {%8,%9}, {%0,%1,%2,%3};"
                        : "+f"(acc[mt][nt][0]), "+f"(acc[mt][nt][1]),
                          "+f"(acc[mt][nt][2]), "+f"(acc[mt][nt][3])
                        : "r"(af[mt][0]), "r"(af[mt][1]), "r"(af[mt][2]), "r"(af[mt][3]),
                          "r"(bf[nt][0]), "r"(bf[nt][1]));
                }
        }
        __syncthreads();
    }

#pragma unroll
    for (int mt = 0; mt < 2; mt++) {
        int r0 = row0 + wrow * 32 + mt * 16 + g;
#pragma unroll
        for (int nt = 0; nt < 8; nt++) {
            int cc = col0 + wcol * 64 + nt * 8 + c4 * 2;
            float b0 = bias[cc], b1 = bias[cc + 1];
            float2 v0 = make_float2(acc[mt][nt][0] + b0, acc[mt][nt][1] + b1);
            float2 v1 = make_float2(acc[mt][nt][2] + b0, acc[mt][nt][3] + b1);
            *reinterpret_cast<float2*>(&C[(size_t)r0 * HH + cc])       = v0;
            *reinterpret_cast<float2*>(&C[(size_t)(r0 + 8) * HH + cc]) = v1;
        }
    }
}

// ---------------- edge GEMM + fused lattice merge ----------------
// CTA tile: rows [row0,row0+128) of [B*W] space = 16 batches x 8 words,
// cols [col0,col0+128). Computes edge projection in regs, then the full
// lattice softmax-merge for its 16 batches x 128 h — writes h1/c directly.
__global__ void __launch_bounds__(256)
gemm_edge_fused(const __half* __restrict__ A,    // ac16 [B*W, 512]
                const __half* __restrict__ W,    // wt16+G_LC [512,512]
                const float*  __restrict__ bias, // b_lc
                const float*  __restrict__ pre,  // 4 chunks
                const float*  __restrict__ allc, // fp32 [B,W,H]
                const int*    __restrict__ numw,
                float*        __restrict__ out)
{
    extern __shared__ __align__(16) char sm_[];

    const int bid  = blockIdx.x;
    const int row0 = (bid >> 2) * 128;
    const int col0 = (bid & 3) * 128;
    const int b0   = row0 >> 3;          // first batch of this tile

    const int tid  = threadIdx.x;
    const int wid  = tid >> 5;
    const int lane = tid & 31;
    const int wrow = wid >> 1;
    const int wcol = wid & 1;
    const int g  = lane >> 2;
    const int c4 = lane & 3;
    const int lm_row = lane & 15;
    const int lm_col = (lane >> 4) * 16;

    float acc[2][8][4];
#pragma unroll
    for (int mt = 0; mt < 2; mt++)
#pragma unroll
        for (int nt = 0; nt < 8; nt++)
#pragma unroll
            for (int r = 0; r < 4; r++) acc[mt][nt][r] = 0.f;

    const uint32_t smb = smem_u32(sm_);
    const size_t CH = (size_t)BB * HH;

    auto load_stage = [&](int s, int kb) {
        uint32_t sAb = smb + s * STAGE_B;
        uint32_t sBb = sAb + TILE_B;
        int k0 = kb * BKH;
#pragma unroll
        for (int i = 0; i < 4; i++) {
            int id = tid + i * 256;
            int r = id >> 3, ch = id & 7;
            cp16(sAb + r * ROWB + ch * 16,
                 A + (size_t)(row0 + r) * HH + k0 + ch * 8, true);
        }
#pragma unroll
        for (int i = 0; i < 4; i++) {
            int id = tid + i * 256;
            int r = id >> 3, ch = id & 7;
            cp16(sBb + r * ROWB + ch * 16,
                 W + (size_t)(col0 + r) * HH + k0 + ch * 8, true);
        }
        CP_COMMIT();
    };

    load_stage(0, 0);
    const int nk = HH / BKH;   // 8

    for (int kb = 0; kb < nk; kb++) {
        if (kb + 1 < nk) { load_stage((kb + 1) & 1, kb + 1); CP_WAIT(1); }
        else             { CP_WAIT(0); }
        __syncthreads();

        const uint32_t As = smb + (kb & 1) * STAGE_B;
        const uint32_t Bs = As + TILE_B;

#pragma unroll
        for (int kk = 0; kk < 4; kk++) {
            uint32_t af[2][4], bf[8][2];
            const int kby = kk * 32 + lm_col;
#pragma unroll
            for (int mt = 0; mt < 2; mt++) {
                uint32_t ad = As + (wrow * 32 + mt * 16 + lm_row) * ROWB + kby;
                LDSM_X4(af[mt][0], af[mt][1], af[mt][2], af[mt][3], ad);
            }
#pragma unroll
            for (int ntp = 0; ntp < 4; ntp++) {
                uint32_t bd = Bs + (wcol * 64 + ntp * 16 + lm_row) * ROWB + kby;
                LDSM_X4(bf[2 * ntp][0], bf[2 * ntp + 1][0],
                        bf[2 * ntp][1], bf[2 * ntp + 1][1], bd);
            }
#pragma unroll
            for (int mt = 0; mt < 2; mt++)
#pragma unroll
                for (int nt = 0; nt < 8; nt++) {
                    asm volatile(
                        "mma.sync.aligned.m16n8k16.row.col.f32.f16.f16.f32 "
                        "{%0,%1,%2,%3}, {%4,%5,%6,%7}, {%8,%9}, {%0,%1,%2,%3};"
                        : "+f"(acc[mt][nt][0]), "+f"(acc[mt][nt][1]),
                          "+f"(acc[mt][nt][2]), "+f"(acc[mt][nt][3])
                        : "r"(af[mt][0]), "r"(af[mt][1]), "r"(af[mt][2]), "r"(af[mt][3]),
                          "r"(bf[nt][0]), "r"(bf[nt][1]));
                }
        }
        __syncthreads();
    }

    // -------- fused lattice merge --------
    // smem: ex[128][66] f32 (33792 f) + lxb[16][128] f32 (2048 f) = 41984 f
    float* exs = reinterpret_cast<float*>(sm_);
    float* lxb = exs + 128 * 66;

    // lxb[b][c] = lx_proj[b0+b, col0+c] + b_lc[col0+c]
    for (int i = tid; i < 16 * 128; i += 256) {
        int b = i >> 7, c = i & 127;
        lxb[i] = pre[3 * CH + (size_t)(b0 + b) * HH + col0 + c] + bias[col0 + c];
    }
    __syncthreads();

#pragma unroll
    for (int half = 0; half < 2; half++) {
        if (wcol == half) {
#pragma unroll
            for (int mt = 0; mt < 2; mt++) {
#pragma unroll
                for (int nt = 0; nt < 8; nt++) {
#pragma unroll
                    for (int idx = 0; idx < 4; idx++) {
                        int r  = wrow * 32 + mt * 16 + g + ((idx >> 1) << 3);
                        int cc = wcol * 64 + nt * 8 + c4 * 2 + (idx & 1);
                        float v = acc[mt][nt][idx] + lxb[(r >> 3) * 128 + cc];
                        float ie = 1.f / (1.f + expf(-v));
                        exs[r * 66 + (cc - half * 64)] = expf(ie);
                    }
                }
            }
        }
        __syncthreads();

        // reduce: 16 batches x 64 cols = 1024 outputs, 4 per thread
#pragma unroll
        for (int k = 0; k < 4; k++) {
            int o = tid + k * 256;
            int b = o >> 6, c = o & 63;
            int gb = b0 + b;
            int gc = col0 + half * 64 + c;
            int nw = numw[gb];

            float sum_e = 0.f, sum_ec = 0.f;
            for (int w = 0; w < nw; w++) {
                float ex = exs[(b * 8 + w) * 66 + c];
                float cw = allc[(size_t)(row0 + b * 8 + w) * HH + gc];
                sum_e  += ex;
                sum_ec += ex * cw;
            }

            size_t pi = (size_t)gb * HH + gc;
            float iv = 1.f / (1.f + expf(-pre[pi]));
            float gv = tanhf(pre[CH + pi]);
            float ov = 1.f / (1.f + expf(-pre[2 * CH + pi]));
            float ei = expf(iv);
            float cval = (nw > 0) ? (sum_ec + ei * gv) / (ei + sum_e) : gv;
            out[pi]      = ov * tanhf(cval);
            out[CH + pi] = cval;
        }
        __syncthreads();
    }
}

// ---------------- launch ----------------
extern "C" void kernel_launch(void* const* d_in, const int* in_sizes, int n_in,
                              void* d_out, int out_size)
{
    const float* x    = (const float*)d_in[0];
    const float* h0   = (const float*)d_in[1];
    /* d_in[2] = c0 : unused */
    const float* allc = (const float*)d_in[3];
    const int*   numw = (const int*)  d_in[4];

    const float* w_ii = (const float*)d_in[5];  const float* b_ii = (const float*)d_in[6];
    const float* w_hi = (const float*)d_in[7];  const float* b_hi = (const float*)d_in[8];
    /* 9..12: dead */
    const float* w_ig = (const float*)d_in[13]; const float* b_ig = (const float*)d_in[14];
    const float* w_hg = (const float*)d_in[15]; const float* b_hg = (const float*)d_in[16];
    const float* w_io = (const float*)d_in[17]; const float* b_io = (const float*)d_in[18];
    const float* w_ho = (const float*)d_in[19]; const float* b_ho = (const float*)d_in[20];
    const float* w_lx = (const float*)d_in[21]; const float* b_lx = (const float*)d_in[22];
    const float* w_lc = (const float*)d_in[23]; const float* b_lc = (const float*)d_in[24];

    __half *xh, *ac16, *wt16;
    float *pre, *bsum;
    cudaGetSymbolAddress((void**)&xh,   g_xh);
    cudaGetSymbolAddress((void**)&ac16, g_ac16);
    cudaGetSymbolAddress((void**)&wt16, g_wt16);
    cudaGetSymbolAddress((void**)&pre,  g_pre);
    cudaGetSymbolAddress((void**)&bsum, g_bsum);

    cudaFuncSetAttribute(gemm_fp16,
                         cudaFuncAttributeMaxDynamicSharedMemorySize, SMEM_BYTES);
    cudaFuncSetAttribute(gemm_edge_fused,
                         cudaFuncAttributeMaxDynamicSharedMemorySize, SMEM_BYTES);

    const size_t CH = (size_t)BB * HH;

    // ---- convert activations to fp16 (packed [x | h0]) ----
    {
        int n4 = BB * (DD / 4);
        conv_pack<<<(n4 + 255) / 256, 256>>>(x, xh, DD / 4, DD, KC, 0, n4);
        n4 = BB * (HH / 4);
        conv_pack<<<(n4 + 255) / 256, 256>>>(h0, xh, HH / 4, HH, KC, KXP, n4);
        n4 = BB * WW * (HH / 4);
        conv_pack<<<(n4 + 255) / 256, 256>>>(allc, ac16, HH / 4, HH, HH, 0, n4);
    }
    // ---- weights: convert + transpose into [N,Kpad] fp16 ----
    {
        TSet ts;
        ts.s[0] = w_ii; ts.K[0] = DD; ts.dst[0] = G_I;        ts.strideW[0] = KC;
        ts.s[1] = w_hi; ts.K[1] = HH; ts.dst[1] = G_I + KXP;  ts.strideW[1] = KC;
        ts.s[2] = w_ig; ts.K[2] = DD; ts.dst[2] = G_G;        ts.strideW[2] = KC;
        ts.s[3] = w_hg; ts.K[3] = HH; ts.dst[3] = G_G + KXP;  ts.strideW[3] = KC;
        ts.s[4] = w_io; ts.K[4] = DD; ts.dst[4] = G_O;        ts.strideW[4] = KC;
        ts.s[5] = w_ho; ts.K[5] = HH; ts.dst[5] = G_O + KXP;  ts.strideW[5] = KC;
        ts.s[6] = w_lx; ts.K[6] = DD; ts.dst[6] = G_LX;       ts.strideW[6] = KXP;
        ts.s[7] = w_lc; ts.K[7] = HH; ts.dst[7] = G_LC;       ts.strideW[7] = HH;
        prep_w<<<dim3(16, 16, 8), 256>>>(ts, wt16);
        bias_sum<<<2, 256>>>(b_ii, b_hi, b_ig, b_hg, b_io, b_ho, bsum);
    }

    // ---- launch A: gates + lx (4 jobs, 1024 CTAs) ----
    Jobs4 jb;
    jb.A[0] = xh; jb.W[0] = wt16 + G_I;  jb.bias[0] = bsum;          jb.C[0] = pre;          jb.sA[0] = KC; jb.sW[0] = KC;  jb.nk[0] = KC / BKH;  jb.start[0] = 0;
    jb.A[1] = xh; jb.W[1] = wt16 + G_G;  jb.bias[1] = bsum + HH;     jb.C[1] = pre + CH;     jb.sA[1] = KC; jb.sW[1] = KC;  jb.nk[1] = KC / BKH;  jb.start[1] = 256;
    jb.A[2] = xh; jb.W[2] = wt16 + G_O;  jb.bias[2] = bsum + 2 * HH; jb.C[2] = pre + 2 * CH; jb.sA[2] = KC; jb.sW[2] = KC;  jb.nk[2] = KC / BKH;  jb.start[2] = 512;
    jb.A[3] = xh; jb.W[3] = wt16 + G_LX; jb.bias[3] = b_lx;          jb.C[3] = pre + 3 * CH; jb.sA[3] = KC; jb.sW[3] = KXP; jb.nk[3] = KXP / BKH; jb.start[3] = 768;
    gemm_fp16<<<1024, 256, SMEM_BYTES>>>(jb);

    // ---- launch B: edge GEMM + fused lattice merge (2048 CTAs) ----
    gemm_edge_fused<<<2048, 256, SMEM_BYTES>>>(ac16, wt16 + G_LC, b_lc,
                                               pre, allc, numw, (float*)d_out);
}

// round 12
// speedup vs baseline: 1.8437x; 1.8437x over previous
#include <cuda_runtime.h>
#include <cuda_fp16.h>
#include <cstdint>

// Problem constants
#define BB 8192
#define DD 300
#define HH 512
#define WW 8
#define KC 832          // combined K: 320 (x, padded from 300) + 512 (h0)
#define KXP 320         // padded x-only K
#define MW (BB * WW)    // 65536 worst-case edge rows

// ---------------- scratch (no allocations allowed) ----------------
__device__ __half g_xh[(size_t)BB * KC];         // packed fp16 [x | h0]
__device__ __half g_ac16[(size_t)MW * HH];       // fp16 COMPACTED allc rows
__device__ __half g_wt16[1703936];               // fp16 weights [N,Kpad]
#define G_I  0
#define G_G  425984
#define G_O  851968
#define G_LX 1277952
#define G_LC 1441792
__device__ float g_pre[(size_t)4 * BB * HH];     // ipre, gpre, opre, lxproj
__device__ float g_edge[(size_t)MW * HH];        // compacted edge projections
__device__ float g_bsum[3 * HH];
__device__ int   g_prefix[BB + 1];               // exclusive scan of nw; [BB]=total
__device__ int   g_idx[MW];                      // compact row -> b*8+w (conv only)

// ---------------- helpers ----------------
__device__ __forceinline__ uint32_t smem_u32(const void* p) {
    uint32_t a;
    asm("{ .reg .u64 t; cvta.to.shared.u64 t, %1; cvt.u32.u64 %0, t; }"
        : "=r"(a) : "l"(p));
    return a;
}
__device__ __forceinline__ void cp16(uint32_t dst, const void* src, bool pred) {
    asm volatile("cp.async.cg.shared.global [%0], [%1], 16, %2;"
                 :: "r"(dst), "l"(src), "r"(pred ? 16 : 0));
}
#define CP_COMMIT() asm volatile("cp.async.commit_group;")
#define CP_WAIT(n)  asm volatile("cp.async.wait_group %0;" :: "n"(n))
#define LDSM_X4(r0, r1, r2, r3, addr) \
    asm volatile("ldmatrix.sync.aligned.m8n8.x4.shared.b16 {%0,%1,%2,%3}, [%4];" \
                 : "=r"(r0), "=r"(r1), "=r"(r2), "=r"(r3) : "r"(addr))

// ---------------- prep kernels ----------------
__global__ void __launch_bounds__(1024)
scan_nw(const int* __restrict__ numw, int* __restrict__ prefix)
{
    __shared__ int s[1024];
    int tid = threadIdx.x;
    int vals[8], sum = 0;
#pragma unroll
    for (int i = 0; i < 8; i++) { vals[i] = numw[tid * 8 + i]; sum += vals[i]; }
    s[tid] = sum;
    __syncthreads();
    for (int off = 1; off < 1024; off <<= 1) {
        int v = (tid >= off) ? s[tid - off] : 0;
        __syncthreads();
        s[tid] += v;
        __syncthreads();
    }
    int base = (tid > 0) ? s[tid - 1] : 0;
#pragma unroll
    for (int i = 0; i < 8; i++) { prefix[tid * 8 + i] = base; base += vals[i]; }
    if (tid == 1023) prefix[BB] = base;
}

__global__ void __launch_bounds__(256)
fill_idx(int* __restrict__ idx)
{
    int i = blockIdx.x * 256 + threadIdx.x;
    if (i < MW) idx[i] = 0;
}

__global__ void __launch_bounds__(256)
build_idx(const int* __restrict__ numw, const int* __restrict__ prefix,
          int* __restrict__ idx)
{
    int b = blockIdx.x * 256 + threadIdx.x;
    if (b >= BB) return;
    int base = prefix[b], nw = numw[b];
    for (int w = 0; w < nw; w++) idx[base + w] = b * WW + w;
}

__global__ void __launch_bounds__(256)
conv_pack(const float* __restrict__ src, __half* __restrict__ dst,
          int f4_per_row, int src_stride, int dst_stride, int dst_off, int n4)
{
    int i = blockIdx.x * blockDim.x + threadIdx.x;
    if (i >= n4) return;
    int row = i / f4_per_row, c = i - row * f4_per_row;
    float4 v = *reinterpret_cast<const float4*>(src + (size_t)row * src_stride + c * 4);
    __half2 h01 = __floats2half2_rn(v.x, v.y);
    __half2 h23 = __floats2half2_rn(v.z, v.w);
    uint2 o = make_uint2(*reinterpret_cast<uint32_t*>(&h01),
                         *reinterpret_cast<uint32_t*>(&h23));
    *reinterpret_cast<uint2*>(dst + (size_t)row * dst_stride + dst_off + c * 4) = o;
}

// gather+convert live allc rows into COMPACT order: ac16[r] = fp16(allc[idx[r]])
__global__ void __launch_bounds__(256)
conv_gather(const float* __restrict__ allc, const int* __restrict__ idx,
            const int* __restrict__ prefix, __half* __restrict__ dst)
{
    int Mc = prefix[BB];
    int i = blockIdx.x * 256 + threadIdx.x;
    int r = i >> 7;
    if (r >= Mc) return;
    int c = i & 127;
    float4 v = reinterpret_cast<const float4*>(allc)[(size_t)idx[r] * 128 + c];
    __half2 h01 = __floats2half2_rn(v.x, v.y);
    __half2 h23 = __floats2half2_rn(v.z, v.w);
    uint2 o = make_uint2(*reinterpret_cast<uint32_t*>(&h01),
                         *reinterpret_cast<uint32_t*>(&h23));
    *reinterpret_cast<uint2*>(dst + (size_t)r * HH + c * 4) = o;
}

struct TSet { const float* s[8]; int K[8]; int dst[8]; int strideW[8]; };

__global__ void __launch_bounds__(256)
prep_w(TSet ts, __half* __restrict__ wt)
{
    int z = blockIdx.z;
    int K = ts.K[z];
    int k0 = blockIdx.y * 32;
    if (k0 >= K) return;
    int n0 = blockIdx.x * 32;

    __shared__ float s[32][33];
    int tx = threadIdx.x & 31, ty = threadIdx.x >> 5;
#pragma unroll
    for (int i = 0; i < 4; i++) {
        int k = k0 + ty + 8 * i;
        s[ty + 8 * i][tx] = (k < K) ? ts.s[z][(size_t)k * HH + n0 + tx] : 0.f;
    }
    __syncthreads();
#pragma unroll
    for (int i = 0; i < 4; i++) {
        int n = n0 + ty + 8 * i;
        int kk = k0 + tx;
        if (kk < K)
            wt[(size_t)ts.dst[z] + (size_t)n * ts.strideW[z] + kk] =
                __float2half_rn(s[tx][ty + 8 * i]);
    }
}

__global__ void __launch_bounds__(256)
bias_sum(const float* a0, const float* b0, const float* a1, const float* b1,
         const float* a2, const float* b2, float* out)
{
    int i = blockIdx.x * blockDim.x + threadIdx.x;
    if (i >= HH) return;
    out[i]          = a0[i] + b0[i];
    out[HH + i]     = a1[i] + b1[i];
    out[2 * HH + i] = a2[i] + b2[i];
}

// ---------------- fp16 GEMM: 5 jobs; job 4 = compacted edge ----------------
struct Jobs5 {
    const __half* A[5];
    const __half* W[5];
    const float*  bias[5];
    float*        C[5];
    int           sA[5], sW[5], nk[5], start[5];
};

#define BKH 64
#define ROWB 144
#define TILE_B (128 * ROWB)
#define STAGE_B (2 * TILE_B)
#define SMEM_BYTES (2 * STAGE_B)   // 73728

__global__ void __launch_bounds__(256)
gemm_fp16(Jobs5 jb, const int* __restrict__ prefix)
{
    extern __shared__ __align__(16) char sm_[];

    const int bid = blockIdx.x;
    int j = 0;
#pragma unroll
    for (int t = 1; t < 5; t++) if (bid >= jb.start[t]) j = t;

    const __half* __restrict__ A    = jb.A[j];
    const __half* __restrict__ W    = jb.W[j];
    const float*  __restrict__ bias = jb.bias[j];
    float*        __restrict__ C    = jb.C[j];
    const int sA = jb.sA[j], sW = jb.sW[j], nk = jb.nk[j];

    const int local = bid - jb.start[j];
    const int row0 = (local >> 2) * 128;
    const int col0 = (local & 3) * 128;

    // edge job: rows beyond Mc are dead — skip whole tiles, clamp loads,
    // predicate stores. A (ac16) is ALREADY compacted: read rows directly.
    int Mc = 0x7fffffff;
    if (j == 4) {
        Mc = prefix[BB];
        if (row0 >= Mc) return;          // uniform per CTA
    }

    const int tid  = threadIdx.x;
    const int wid  = tid >> 5;
    const int lane = tid & 31;
    const int wrow = wid >> 1;
    const int wcol = wid & 1;
    const int g  = lane >> 2;
    const int c4 = lane & 3;
    const int lm_row = lane & 15;
    const int lm_col = (lane >> 4) * 16;

    float acc[2][8][4];
#pragma unroll
    for (int mt = 0; mt < 2; mt++)
#pragma unroll
        for (int nt = 0; nt < 8; nt++)
#pragma unroll
            for (int r = 0; r < 4; r++) acc[mt][nt][r] = 0.f;

    const uint32_t smb = smem_u32(sm_);
    const int maxrow = (Mc == 0x7fffffff) ? 0x7fffffff : (Mc - 1);

    auto load_stage = [&](int s, int kb) {
        uint32_t sAb = smb + s * STAGE_B;
        uint32_t sBb = sAb + TILE_B;
        int k0 = kb * BKH;
#pragma unroll
        for (int i = 0; i < 4; i++) {
            int id = tid + i * 256;
            int r = id >> 3, ch = id & 7;
            int srow = row0 + r;
            if (srow > maxrow) srow = maxrow;   // clamp: valid addr, data unused
            cp16(sAb + r * ROWB + ch * 16,
                 A + (size_t)srow * sA + k0 + ch * 8, true);
        }
#pragma unroll
        for (int i = 0; i < 4; i++) {
            int id = tid + i * 256;
            int r = id >> 3, ch = id & 7;
            cp16(sBb + r * ROWB + ch * 16,
                 W + (size_t)(col0 + r) * sW + k0 + ch * 8, true);
        }
        CP_COMMIT();
    };

    load_stage(0, 0);

    for (int kb = 0; kb < nk; kb++) {
        if (kb + 1 < nk) { load_stage((kb + 1) & 1, kb + 1); CP_WAIT(1); }
        else             { CP_WAIT(0); }
        __syncthreads();

        const uint32_t As = smb + (kb & 1) * STAGE_B;
        const uint32_t Bs = As + TILE_B;

#pragma unroll
        for (int kk = 0; kk < 4; kk++) {
            uint32_t af[2][4], bf[8][2];
            const int kby = kk * 32 + lm_col;
#pragma unroll
            for (int mt = 0; mt < 2; mt++) {
                uint32_t ad = As + (wrow * 32 + mt * 16 + lm_row) * ROWB + kby;
                LDSM_X4(af[mt][0], af[mt][1], af[mt][2], af[mt][3], ad);
            }
#pragma unroll
            for (int ntp = 0; ntp < 4; ntp++) {
                uint32_t bd = Bs + (wcol * 64 + ntp * 16 + lm_row) * ROWB + kby;
                LDSM_X4(bf[2 * ntp][0], bf[2 * ntp + 1][0],
                        bf[2 * ntp][1], bf[2 * ntp + 1][1], bd);
            }
#pragma unroll
            for (int mt = 0; mt < 2; mt++)
#pragma unroll
                for (int nt = 0; nt < 8; nt++) {
                    asm volatile(
                        "mma.sync.aligned.m16n8k16.row.col.f32.f16.f16.f32 "
                        "{%0,%1,%2,%3}, {%4,%5,%6,%7}, {%8,%9}, {%0,%1,%2,%3};"
                        : "+f"(acc[mt][nt][0]), "+f"(acc[mt][nt][1]),
                          "+f"(acc[mt][nt][2]), "+f"(acc[mt][nt][3])
                        : "r"(af[mt][0]), "r"(af[mt][1]), "r"(af[mt][2]), "r"(af[mt][3]),
                          "r"(bf[nt][0]), "r"(bf[nt][1]));
                }
        }
        __syncthreads();
    }

#pragma unroll
    for (int mt = 0; mt < 2; mt++) {
        int r0 = row0 + wrow * 32 + mt * 16 + g;
#pragma unroll
        for (int nt = 0; nt < 8; nt++) {
            int cc = col0 + wcol * 64 + nt * 8 + c4 * 2;
            float b0 = bias[cc], b1 = bias[cc + 1];
            float2 v0 = make_float2(acc[mt][nt][0] + b0, acc[mt][nt][1] + b1);
            float2 v1 = make_float2(acc[mt][nt][2] + b0, acc[mt][nt][3] + b1);
            if (r0 < Mc)
                *reinterpret_cast<float2*>(&C[(size_t)r0 * HH + cc]) = v0;
            if (r0 + 8 < Mc)
                *reinterpret_cast<float2*>(&C[(size_t)(r0 + 8) * HH + cc]) = v1;
        }
    }
}

// ---------------- fused lattice-LSTM epilogue (float4) ----------------
__global__ void __launch_bounds__(256)
lattice_epilogue(const float* __restrict__ pre,   // ipre,gpre,opre,lx
                 const float* __restrict__ edgec, // compacted [Mc,512]
                 const float* __restrict__ allc,  // fp32 [B,W,H]
                 const int*   __restrict__ prefix,
                 const int*   __restrict__ numw,
                 float* __restrict__ out)
{
    const size_t CH4 = (size_t)BB * HH / 4;
    size_t i4 = (size_t)blockIdx.x * blockDim.x + threadIdx.x;
    if (i4 >= CH4) return;
    int b = (int)(i4 >> 7);

    const float4* pre4 = reinterpret_cast<const float4*>(pre);
    float4 ipre = pre4[i4];
    float4 gpre = pre4[CH4 + i4];
    float4 opre = pre4[2 * CH4 + i4];
    float4 lx   = pre4[3 * CH4 + i4];

    float iv[4], gv[4], ov[4], lxv[4];
    iv[0] = 1.f / (1.f + expf(-ipre.x)); iv[1] = 1.f / (1.f + expf(-ipre.y));
    iv[2] = 1.f / (1.f + expf(-ipre.z)); iv[3] = 1.f / (1.f + expf(-ipre.w));
    gv[0] = tanhf(gpre.x); gv[1] = tanhf(gpre.y);
    gv[2] = tanhf(gpre.z); gv[3] = tanhf(gpre.w);
    ov[0] = 1.f / (1.f + expf(-opre.x)); ov[1] = 1.f / (1.f + expf(-opre.y));
    ov[2] = 1.f / (1.f + expf(-opre.z)); ov[3] = 1.f / (1.f + expf(-opre.w));
    lxv[0] = lx.x; lxv[1] = lx.y; lxv[2] = lx.z; lxv[3] = lx.w;

    int nw = numw[b];
    int pb = prefix[b];
    float sum_e[4]  = {0.f, 0.f, 0.f, 0.f};
    float sum_ec[4] = {0.f, 0.f, 0.f, 0.f};

    size_t h4 = i4 & 127;
    const float4* edge4 = reinterpret_cast<const float4*>(edgec);
    const float4* allc4 = reinterpret_cast<const float4*>(allc);

    for (int w = 0; w < nw; w++) {
        float4 ed = edge4[((size_t)(pb + w)) * 128 + h4];
        float4 ac = allc4[((size_t)(b * WW + w)) * 128 + h4];
        float prev[4] = {lxv[0] + ed.x, lxv[1] + ed.y, lxv[2] + ed.z, lxv[3] + ed.w};
        float av[4]   = {ac.x, ac.y, ac.z, ac.w};
#pragma unroll
        for (int jj = 0; jj < 4; jj++) {
            float ie = 1.f / (1.f + expf(-prev[jj]));
            float ex = expf(ie);
            sum_e[jj]  += ex;
            sum_ec[jj] += ex * av[jj];
        }
    }

    float4 hout, cout;
    float cv[4];
#pragma unroll
    for (int jj = 0; jj < 4; jj++) {
        float ei = expf(iv[jj]);
        float c;
        if (nw > 0) c = (sum_ec[jj] + ei * gv[jj]) / (ei + sum_e[jj]);
        else        c = gv[jj];
        cv[jj] = c;
    }
    hout.x = ov[0] * tanhf(cv[0]); hout.y = ov[1] * tanhf(cv[1]);
    hout.z = ov[2] * tanhf(cv[2]); hout.w = ov[3] * tanhf(cv[3]);
    cout.x = cv[0]; cout.y = cv[1]; cout.z = cv[2]; cout.w = cv[3];

    float4* out4 = reinterpret_cast<float4*>(out);
    out4[i4]       = hout;
    out4[CH4 + i4] = cout;
}

// ---------------- launch ----------------
extern "C" void kernel_launch(void* const* d_in, const int* in_sizes, int n_in,
                              void* d_out, int out_size)
{
    const float* x    = (const float*)d_in[0];
    const float* h0   = (const float*)d_in[1];
    /* d_in[2] = c0 : unused */
    const float* allc = (const float*)d_in[3];
    const int*   numw = (const int*)  d_in[4];

    const float* w_ii = (const float*)d_in[5];  const float* b_ii = (const float*)d_in[6];
    const float* w_hi = (const float*)d_in[7];  const float* b_hi = (const float*)d_in[8];
    /* 9..12: dead */
    const float* w_ig = (const float*)d_in[13]; const float* b_ig = (const float*)d_in[14];
    const float* w_hg = (const float*)d_in[15]; const float* b_hg = (const float*)d_in[16];
    const float* w_io = (const float*)d_in[17]; const float* b_io = (const float*)d_in[18];
    const float* w_ho = (const float*)d_in[19]; const float* b_ho = (const float*)d_in[20];
    const float* w_lx = (const float*)d_in[21]; const float* b_lx = (const float*)d_in[22];
    const float* w_lc = (const float*)d_in[23]; const float* b_lc = (const float*)d_in[24];

    __half *xh, *ac16, *wt16;
    float *pre, *edge, *bsum;
    int *prefix, *idx;
    cudaGetSymbolAddress((void**)&xh,     g_xh);
    cudaGetSymbolAddress((void**)&ac16,   g_ac16);
    cudaGetSymbolAddress((void**)&wt16,   g_wt16);
    cudaGetSymbolAddress((void**)&pre,    g_pre);
    cudaGetSymbolAddress((void**)&edge,   g_edge);
    cudaGetSymbolAddress((void**)&bsum,   g_bsum);
    cudaGetSymbolAddress((void**)&prefix, g_prefix);
    cudaGetSymbolAddress((void**)&idx,    g_idx);

    cudaFuncSetAttribute(gemm_fp16,
                         cudaFuncAttributeMaxDynamicSharedMemorySize, SMEM_BYTES);

    const size_t CH = (size_t)BB * HH;

    // ---- ragged compaction metadata ----
    scan_nw<<<1, 1024>>>(numw, prefix);
    fill_idx<<<MW / 256, 256>>>(idx);
    build_idx<<<BB / 256, 256>>>(numw, prefix, idx);

    // ---- convert activations to fp16 ----
    {
        int n4 = BB * (DD / 4);
        conv_pack<<<(n4 + 255) / 256, 256>>>(x, xh, DD / 4, DD, KC, 0, n4);
        n4 = BB * (HH / 4);
        conv_pack<<<(n4 + 255) / 256, 256>>>(h0, xh, HH / 4, HH, KC, KXP, n4);
        // live allc rows only, written in compact order
        conv_gather<<<MW * 128 / 256, 256>>>(allc, idx, prefix, ac16);
    }
    // ---- weights: convert + transpose into [N,Kpad] fp16 ----
    {
        TSet ts;
        ts.s[0] = w_ii; ts.K[0] = DD; ts.dst[0] = G_I;        ts.strideW[0] = KC;
        ts.s[1] = w_hi; ts.K[1] = HH; ts.dst[1] = G_I + KXP;  ts.strideW[1] = KC;
        ts.s[2] = w_ig; ts.K[2] = DD; ts.dst[2] = G_G;        ts.strideW[2] = KC;
        ts.s[3] = w_hg; ts.K[3] = HH; ts.dst[3] = G_G + KXP;  ts.strideW[3] = KC;
        ts.s[4] = w_io; ts.K[4] = DD; ts.dst[4] = G_O;        ts.strideW[4] = KC;
        ts.s[5] = w_ho; ts.K[5] = HH; ts.dst[5] = G_O + KXP;  ts.strideW[5] = KC;
        ts.s[6] = w_lx; ts.K[6] = DD; ts.dst[6] = G_LX;       ts.strideW[6] = KXP;
        ts.s[7] = w_lc; ts.K[7] = HH; ts.dst[7] = G_LC;       ts.strideW[7] = HH;
        prep_w<<<dim3(16, 16, 8), 256>>>(ts, wt16);
        bias_sum<<<2, 256>>>(b_ii, b_hi, b_ig, b_hg, b_io, b_ho, bsum);
    }

    // ---- one fp16 GEMM launch: 5 jobs, 3072 CTAs (edge tiles early-exit) ----
    Jobs5 jb;
    jb.A[0] = xh;   jb.W[0] = wt16 + G_I;  jb.bias[0] = bsum;          jb.C[0] = pre;          jb.sA[0] = KC; jb.sW[0] = KC;  jb.nk[0] = KC / BKH;  jb.start[0] = 0;
    jb.A[1] = xh;   jb.W[1] = wt16 + G_G;  jb.bias[1] = bsum + HH;     jb.C[1] = pre + CH;     jb.sA[1] = KC; jb.sW[1] = KC;  jb.nk[1] = KC / BKH;  jb.start[1] = 256;
    jb.A[2] = xh;   jb.W[2] = wt16 + G_O;  jb.bias[2] = bsum + 2 * HH; jb.C[2] = pre + 2 * CH; jb.sA[2] = KC; jb.sW[2] = KC;  jb.nk[2] = KC / BKH;  jb.start[2] = 512;
    jb.A[3] = xh;   jb.W[3] = wt16 + G_LX; jb.bias[3] = b_lx;          jb.C[3] = pre + 3 * CH; jb.sA[3] = KC; jb.sW[3] = KXP; jb.nk[3] = KXP / BKH; jb.start[3] = 768;
    jb.A[4] = ac16; jb.W[4] = wt16 + G_LC; jb.bias[4] = b_lc;          jb.C[4] = edge;         jb.sA[4] = HH; jb.sW[4] = HH;  jb.nk[4] = HH / BKH;  jb.start[4] = 1024;

    gemm_fp16<<<3072, 256, SMEM_BYTES>>>(jb, prefix);

    // ---- fused gates + ragged merge ----
    size_t CH4 = CH / 4;
    lattice_epilogue<<<(int)((CH4 + 255) / 256), 256>>>(pre, edge, allc,
                                                        prefix, numw,
                                                        (float*)d_out);
}

// round 13
// speedup vs baseline: 1.9048x; 1.0331x over previous
#include <cuda_runtime.h>
#include <cuda_fp16.h>
#include <cstdint>

// Problem constants
#define BB 8192
#define DD 300
#define HH 512
#define WW 8
#define KC 832          // combined K: 320 (x, padded from 300) + 512 (h0)
#define KXP 320         // padded x-only K
#define MW (BB * WW)    // 65536 worst-case edge rows

// ---------------- scratch (no allocations allowed) ----------------
__device__ __half g_xh[(size_t)BB * KC];         // packed fp16 [x | h0]
__device__ __half g_ac16[(size_t)MW * HH];       // fp16 COMPACTED allc rows
__device__ __half g_wt16[1703936];               // fp16 weights [N,Kpad]
#define G_I  0
#define G_G  425984
#define G_O  851968
#define G_LX 1277952
#define G_LC 1441792
__device__ __half g_pre[(size_t)4 * BB * HH];    // fp16: ipre, gpre, opre, lxproj
__device__ __half g_edge[(size_t)MW * HH];       // fp16 compacted edge projections
__device__ float g_bsum[3 * HH];
__device__ int   g_prefix[BB + 1];               // exclusive scan of nw; [BB]=total
__device__ int   g_idx[MW];                      // compact row -> b*8+w (conv only)

// ---------------- helpers ----------------
__device__ __forceinline__ uint32_t smem_u32(const void* p) {
    uint32_t a;
    asm("{ .reg .u64 t; cvta.to.shared.u64 t, %1; cvt.u32.u64 %0, t; }"
        : "=r"(a) : "l"(p));
    return a;
}
__device__ __forceinline__ void cp16(uint32_t dst, const void* src, bool pred) {
    asm volatile("cp.async.cg.shared.global [%0], [%1], 16, %2;"
                 :: "r"(dst), "l"(src), "r"(pred ? 16 : 0));
}
#define CP_COMMIT() asm volatile("cp.async.commit_group;")
#define CP_WAIT(n)  asm volatile("cp.async.wait_group %0;" :: "n"(n))
#define LDSM_X4(r0, r1, r2, r3, addr) \
    asm volatile("ldmatrix.sync.aligned.m8n8.x4.shared.b16 {%0,%1,%2,%3}, [%4];" \
                 : "=r"(r0), "=r"(r1), "=r"(r2), "=r"(r3) : "r"(addr))

// ---------------- prep kernels ----------------
__global__ void __launch_bounds__(1024)
scan_nw(const int* __restrict__ numw, int* __restrict__ prefix)
{
    __shared__ int s[1024];
    int tid = threadIdx.x;
    int vals[8], sum = 0;
#pragma unroll
    for (int i = 0; i < 8; i++) { vals[i] = numw[tid * 8 + i]; sum += vals[i]; }
    s[tid] = sum;
    __syncthreads();
    for (int off = 1; off < 1024; off <<= 1) {
        int v = (tid >= off) ? s[tid - off] : 0;
        __syncthreads();
        s[tid] += v;
        __syncthreads();
    }
    int base = (tid > 0) ? s[tid - 1] : 0;
#pragma unroll
    for (int i = 0; i < 8; i++) { prefix[tid * 8 + i] = base; base += vals[i]; }
    if (tid == 1023) prefix[BB] = base;
}

__global__ void __launch_bounds__(256)
fill_idx(int* __restrict__ idx)
{
    int i = blockIdx.x * 256 + threadIdx.x;
    if (i < MW) idx[i] = 0;
}

__global__ void __launch_bounds__(256)
build_idx(const int* __restrict__ numw, const int* __restrict__ prefix,
          int* __restrict__ idx)
{
    int b = blockIdx.x * 256 + threadIdx.x;
    if (b >= BB) return;
    int base = prefix[b], nw = numw[b];
    for (int w = 0; w < nw; w++) idx[base + w] = b * WW + w;
}

__global__ void __launch_bounds__(256)
conv_pack(const float* __restrict__ src, __half* __restrict__ dst,
          int f4_per_row, int src_stride, int dst_stride, int dst_off, int n4)
{
    int i = blockIdx.x * blockDim.x + threadIdx.x;
    if (i >= n4) return;
    int row = i / f4_per_row, c = i - row * f4_per_row;
    float4 v = *reinterpret_cast<const float4*>(src + (size_t)row * src_stride + c * 4);
    __half2 h01 = __floats2half2_rn(v.x, v.y);
    __half2 h23 = __floats2half2_rn(v.z, v.w);
    uint2 o = make_uint2(*reinterpret_cast<uint32_t*>(&h01),
                         *reinterpret_cast<uint32_t*>(&h23));
    *reinterpret_cast<uint2*>(dst + (size_t)row * dst_stride + dst_off + c * 4) = o;
}

// gather+convert live allc rows into COMPACT order: ac16[r] = fp16(allc[idx[r]])
__global__ void __launch_bounds__(256)
conv_gather(const float* __restrict__ allc, const int* __restrict__ idx,
            const int* __restrict__ prefix, __half* __restrict__ dst)
{
    int Mc = prefix[BB];
    int i = blockIdx.x * 256 + threadIdx.x;
    int r = i >> 7;
    if (r >= Mc) return;
    int c = i & 127;
    float4 v = reinterpret_cast<const float4*>(allc)[(size_t)idx[r] * 128 + c];
    __half2 h01 = __floats2half2_rn(v.x, v.y);
    __half2 h23 = __floats2half2_rn(v.z, v.w);
    uint2 o = make_uint2(*reinterpret_cast<uint32_t*>(&h01),
                         *reinterpret_cast<uint32_t*>(&h23));
    *reinterpret_cast<uint2*>(dst + (size_t)r * HH + c * 4) = o;
}

struct TSet { const float* s[8]; int K[8]; int dst[8]; int strideW[8]; };

__global__ void __launch_bounds__(256)
prep_w(TSet ts, __half* __restrict__ wt)
{
    int z = blockIdx.z;
    int K = ts.K[z];
    int k0 = blockIdx.y * 32;
    if (k0 >= K) return;
    int n0 = blockIdx.x * 32;

    __shared__ float s[32][33];
    int tx = threadIdx.x & 31, ty = threadIdx.x >> 5;
#pragma unroll
    for (int i = 0; i < 4; i++) {
        int k = k0 + ty + 8 * i;
        s[ty + 8 * i][tx] = (k < K) ? ts.s[z][(size_t)k * HH + n0 + tx] : 0.f;
    }
    __syncthreads();
#pragma unroll
    for (int i = 0; i < 4; i++) {
        int n = n0 + ty + 8 * i;
        int kk = k0 + tx;
        if (kk < K)
            wt[(size_t)ts.dst[z] + (size_t)n * ts.strideW[z] + kk] =
                __float2half_rn(s[tx][ty + 8 * i]);
    }
}

__global__ void __launch_bounds__(256)
bias_sum(const float* a0, const float* b0, const float* a1, const float* b1,
         const float* a2, const float* b2, float* out)
{
    int i = blockIdx.x * blockDim.x + threadIdx.x;
    if (i >= HH) return;
    out[i]          = a0[i] + b0[i];
    out[HH + i]     = a1[i] + b1[i];
    out[2 * HH + i] = a2[i] + b2[i];
}

// ---------------- fp16 GEMM: 5 jobs; job 4 = compacted edge ----------------
// Outputs stored as fp16 (bias added in fp32 first).
struct Jobs5 {
    const __half* A[5];
    const __half* W[5];
    const float*  bias[5];
    __half*       C[5];
    int           sA[5], sW[5], nk[5], start[5];
};

#define BKH 64
#define ROWB 144
#define TILE_B (128 * ROWB)
#define STAGE_B (2 * TILE_B)
#define SMEM_BYTES (2 * STAGE_B)   // 73728

__global__ void __launch_bounds__(256)
gemm_fp16(Jobs5 jb, const int* __restrict__ prefix)
{
    extern __shared__ __align__(16) char sm_[];

    const int bid = blockIdx.x;
    int j = 0;
#pragma unroll
    for (int t = 1; t < 5; t++) if (bid >= jb.start[t]) j = t;

    const __half* __restrict__ A    = jb.A[j];
    const __half* __restrict__ W    = jb.W[j];
    const float*  __restrict__ bias = jb.bias[j];
    __half*       __restrict__ C    = jb.C[j];
    const int sA = jb.sA[j], sW = jb.sW[j], nk = jb.nk[j];

    const int local = bid - jb.start[j];
    const int row0 = (local >> 2) * 128;
    const int col0 = (local & 3) * 128;

    int Mc = 0x7fffffff;
    if (j == 4) {
        Mc = prefix[BB];
        if (row0 >= Mc) return;          // uniform per CTA
    }

    const int tid  = threadIdx.x;
    const int wid  = tid >> 5;
    const int lane = tid & 31;
    const int wrow = wid >> 1;
    const int wcol = wid & 1;
    const int g  = lane >> 2;
    const int c4 = lane & 3;
    const int lm_row = lane & 15;
    const int lm_col = (lane >> 4) * 16;

    float acc[2][8][4];
#pragma unroll
    for (int mt = 0; mt < 2; mt++)
#pragma unroll
        for (int nt = 0; nt < 8; nt++)
#pragma unroll
            for (int r = 0; r < 4; r++) acc[mt][nt][r] = 0.f;

    const uint32_t smb = smem_u32(sm_);
    const int maxrow = (Mc == 0x7fffffff) ? 0x7fffffff : (Mc - 1);

    auto load_stage = [&](int s, int kb) {
        uint32_t sAb = smb + s * STAGE_B;
        uint32_t sBb = sAb + TILE_B;
        int k0 = kb * BKH;
#pragma unroll
        for (int i = 0; i < 4; i++) {
            int id = tid + i * 256;
            int r = id >> 3, ch = id & 7;
            int srow = row0 + r;
            if (srow > maxrow) srow = maxrow;   // clamp: valid addr, data unused
            cp16(sAb + r * ROWB + ch * 16,
                 A + (size_t)srow * sA + k0 + ch * 8, true);
        }
#pragma unroll
        for (int i = 0; i < 4; i++) {
            int id = tid + i * 256;
            int r = id >> 3, ch = id & 7;
            cp16(sBb + r * ROWB + ch * 16,
                 W + (size_t)(col0 + r) * sW + k0 + ch * 8, true);
        }
        CP_COMMIT();
    };

    load_stage(0, 0);

    for (int kb = 0; kb < nk; kb++) {
        if (kb + 1 < nk) { load_stage((kb + 1) & 1, kb + 1); CP_WAIT(1); }
        else             { CP_WAIT(0); }
        __syncthreads();

        const uint32_t As = smb + (kb & 1) * STAGE_B;
        const uint32_t Bs = As + TILE_B;

#pragma unroll
        for (int kk = 0; kk < 4; kk++) {
            uint32_t af[2][4], bf[8][2];
            const int kby = kk * 32 + lm_col;
#pragma unroll
            for (int mt = 0; mt < 2; mt++) {
                uint32_t ad = As + (wrow * 32 + mt * 16 + lm_row) * ROWB + kby;
                LDSM_X4(af[mt][0], af[mt][1], af[mt][2], af[mt][3], ad);
            }
#pragma unroll
            for (int ntp = 0; ntp < 4; ntp++) {
                uint32_t bd = Bs + (wcol * 64 + ntp * 16 + lm_row) * ROWB + kby;
                LDSM_X4(bf[2 * ntp][0], bf[2 * ntp + 1][0],
                        bf[2 * ntp][1], bf[2 * ntp + 1][1], bd);
            }
#pragma unroll
            for (int mt = 0; mt < 2; mt++)
#pragma unroll
                for (int nt = 0; nt < 8; nt++) {
                    asm volatile(
                        "mma.sync.aligned.m16n8k16.row.col.f32.f16.f16.f32 "
                        "{%0,%1,%2,%3}, {%4,%5,%6,%7}, {%8,%9}, {%0,%1,%2,%3};"
                        : "+f"(acc[mt][nt][0]), "+f"(acc[mt][nt][1]),
                          "+f"(acc[mt][nt][2]), "+f"(acc[mt][nt][3])
                        : "r"(af[mt][0]), "r"(af[mt][1]), "r"(af[mt][2]), "r"(af[mt][3]),
                          "r"(bf[nt][0]), "r"(bf[nt][1]));
                }
        }
        __syncthreads();
    }

    // epilogue: + bias (fp32), convert to fp16, 4-byte stores
#pragma unroll
    for (int mt = 0; mt < 2; mt++) {
        int r0 = row0 + wrow * 32 + mt * 16 + g;
#pragma unroll
        for (int nt = 0; nt < 8; nt++) {
            int cc = col0 + wcol * 64 + nt * 8 + c4 * 2;
            float b0 = bias[cc], b1 = bias[cc + 1];
            __half2 v0 = __floats2half2_rn(acc[mt][nt][0] + b0, acc[mt][nt][1] + b1);
            __half2 v1 = __floats2half2_rn(acc[mt][nt][2] + b0, acc[mt][nt][3] + b1);
            if (r0 < Mc)
                *reinterpret_cast<__half2*>(&C[(size_t)r0 * HH + cc]) = v0;
            if (r0 + 8 < Mc)
                *reinterpret_cast<__half2*>(&C[(size_t)(r0 + 8) * HH + cc]) = v1;
        }
    }
}

// ---------------- fused lattice-LSTM epilogue (fp16 inputs) ----------------
__device__ __forceinline__ void ld4h(const __half* p, float* f) {
    uint2 u = *reinterpret_cast<const uint2*>(p);
    float2 a = __half22float2(*reinterpret_cast<__half2*>(&u.x));
    float2 b = __half22float2(*reinterpret_cast<__half2*>(&u.y));
    f[0] = a.x; f[1] = a.y; f[2] = b.x; f[3] = b.y;
}

__global__ void __launch_bounds__(256)
lattice_epilogue(const __half* __restrict__ pre,   // fp16: ipre,gpre,opre,lx
                 const __half* __restrict__ edgec, // fp16 compacted [Mc,512]
                 const float*  __restrict__ allc,  // fp32 [B,W,H]
                 const int*    __restrict__ prefix,
                 const int*    __restrict__ numw,
                 float* __restrict__ out)           // fp32 [2*B*H]
{
    const size_t CH  = (size_t)BB * HH;
    const size_t CH4 = CH / 4;
    size_t i4 = (size_t)blockIdx.x * blockDim.x + threadIdx.x;
    if (i4 >= CH4) return;
    int b = (int)(i4 >> 7);

    float ipre[4], gpre[4], opre[4], lxv[4];
    ld4h(pre + i4 * 4,          ipre);
    ld4h(pre + CH + i4 * 4,     gpre);
    ld4h(pre + 2 * CH + i4 * 4, opre);
    ld4h(pre + 3 * CH + i4 * 4, lxv);

    float iv[4], gv[4], ov[4];
#pragma unroll
    for (int jj = 0; jj < 4; jj++) {
        iv[jj] = 1.f / (1.f + expf(-ipre[jj]));
        gv[jj] = tanhf(gpre[jj]);
        ov[jj] = 1.f / (1.f + expf(-opre[jj]));
    }

    int nw = numw[b];
    int pb = prefix[b];
    float sum_e[4]  = {0.f, 0.f, 0.f, 0.f};
    float sum_ec[4] = {0.f, 0.f, 0.f, 0.f};

    size_t h4 = i4 & 127;
    const float4* allc4 = reinterpret_cast<const float4*>(allc);

    for (int w = 0; w < nw; w++) {
        float ed[4];
        ld4h(edgec + ((size_t)(pb + w)) * HH + h4 * 4, ed);
        float4 ac = allc4[((size_t)(b * WW + w)) * 128 + h4];
        float av[4] = {ac.x, ac.y, ac.z, ac.w};
#pragma unroll
        for (int jj = 0; jj < 4; jj++) {
            float ie = 1.f / (1.f + expf(-(lxv[jj] + ed[jj])));
            float ex = expf(ie);
            sum_e[jj]  += ex;
            sum_ec[jj] += ex * av[jj];
        }
    }

    float4 hout, cout;
    float cv[4];
#pragma unroll
    for (int jj = 0; jj < 4; jj++) {
        float ei = expf(iv[jj]);
        float c;
        if (nw > 0) c = (sum_ec[jj] + ei * gv[jj]) / (ei + sum_e[jj]);
        else        c = gv[jj];
        cv[jj] = c;
    }
    hout.x = ov[0] * tanhf(cv[0]); hout.y = ov[1] * tanhf(cv[1]);
    hout.z = ov[2] * tanhf(cv[2]); hout.w = ov[3] * tanhf(cv[3]);
    cout.x = cv[0]; cout.y = cv[1]; cout.z = cv[2]; cout.w = cv[3];

    float4* out4 = reinterpret_cast<float4*>(out);
    out4[i4]       = hout;
    out4[CH4 + i4] = cout;
}

// ---------------- launch ----------------
extern "C" void kernel_launch(void* const* d_in, const int* in_sizes, int n_in,
                              void* d_out, int out_size)
{
    const float* x    = (const float*)d_in[0];
    const float* h0   = (const float*)d_in[1];
    /* d_in[2] = c0 : unused */
    const float* allc = (const float*)d_in[3];
    const int*   numw = (const int*)  d_in[4];

    const float* w_ii = (const float*)d_in[5];  const float* b_ii = (const float*)d_in[6];
    const float* w_hi = (const float*)d_in[7];  const float* b_hi = (const float*)d_in[8];
    /* 9..12: dead */
    const float* w_ig = (const float*)d_in[13]; const float* b_ig = (const float*)d_in[14];
    const float* w_hg = (const float*)d_in[15]; const float* b_hg = (const float*)d_in[16];
    const float* w_io = (const float*)d_in[17]; const float* b_io = (const float*)d_in[18];
    const float* w_ho = (const float*)d_in[19]; const float* b_ho = (const float*)d_in[20];
    const float* w_lx = (const float*)d_in[21]; const float* b_lx = (const float*)d_in[22];
    const float* w_lc = (const float*)d_in[23]; const float* b_lc = (const float*)d_in[24];

    __half *xh, *ac16, *wt16, *pre, *edge;
    float *bsum;
    int *prefix, *idx;
    cudaGetSymbolAddress((void**)&xh,     g_xh);
    cudaGetSymbolAddress((void**)&ac16,   g_ac16);
    cudaGetSymbolAddress((void**)&wt16,   g_wt16);
    cudaGetSymbolAddress((void**)&pre,    g_pre);
    cudaGetSymbolAddress((void**)&edge,   g_edge);
    cudaGetSymbolAddress((void**)&bsum,   g_bsum);
    cudaGetSymbolAddress((void**)&prefix, g_prefix);
    cudaGetSymbolAddress((void**)&idx,    g_idx);

    cudaFuncSetAttribute(gemm_fp16,
                         cudaFuncAttributeMaxDynamicSharedMemorySize, SMEM_BYTES);

    const size_t CH = (size_t)BB * HH;

    // ---- ragged compaction metadata ----
    scan_nw<<<1, 1024>>>(numw, prefix);
    fill_idx<<<MW / 256, 256>>>(idx);
    build_idx<<<BB / 256, 256>>>(numw, prefix, idx);

    // ---- convert activations to fp16 ----
    {
        int n4 = BB * (DD / 4);
        conv_pack<<<(n4 + 255) / 256, 256>>>(x, xh, DD / 4, DD, KC, 0, n4);
        n4 = BB * (HH / 4);
        conv_pack<<<(n4 + 255) / 256, 256>>>(h0, xh, HH / 4, HH, KC, KXP, n4);
        conv_gather<<<MW * 128 / 256, 256>>>(allc, idx, prefix, ac16);
    }
    // ---- weights: convert + transpose into [N,Kpad] fp16 ----
    {
        TSet ts;
        ts.s[0] = w_ii; ts.K[0] = DD; ts.dst[0] = G_I;        ts.strideW[0] = KC;
        ts.s[1] = w_hi; ts.K[1] = HH; ts.dst[1] = G_I + KXP;  ts.strideW[1] = KC;
        ts.s[2] = w_ig; ts.K[2] = DD; ts.dst[2] = G_G;        ts.strideW[2] = KC;
        ts.s[3] = w_hg; ts.K[3] = HH; ts.dst[3] = G_G + KXP;  ts.strideW[3] = KC;
        ts.s[4] = w_io; ts.K[4] = DD; ts.dst[4] = G_O;        ts.strideW[4] = KC;
        ts.s[5] = w_ho; ts.K[5] = HH; ts.dst[5] = G_O + KXP;  ts.strideW[5] = KC;
        ts.s[6] = w_lx; ts.K[6] = DD; ts.dst[6] = G_LX;       ts.strideW[6] = KXP;
        ts.s[7] = w_lc; ts.K[7] = HH; ts.dst[7] = G_LC;       ts.strideW[7] = HH;
        prep_w<<<dim3(16, 16, 8), 256>>>(ts, wt16);
        bias_sum<<<2, 256>>>(b_ii, b_hi, b_ig, b_hg, b_io, b_ho, bsum);
    }

    // ---- one fp16 GEMM launch: 5 jobs, 3072 CTAs (edge tiles early-exit) ----
    Jobs5 jb;
    jb.A[0] = xh;   jb.W[0] = wt16 + G_I;  jb.bias[0] = bsum;          jb.C[0] = pre;          jb.sA[0] = KC; jb.sW[0] = KC;  jb.nk[0] = KC / BKH;  jb.start[0] = 0;
    jb.A[1] = xh;   jb.W[1] = wt16 + G_G;  jb.bias[1] = bsum + HH;     jb.C[1] = pre + CH;     jb.sA[1] = KC; jb.sW[1] = KC;  jb.nk[1] = KC / BKH;  jb.start[1] = 256;
    jb.A[2] = xh;   jb.W[2] = wt16 + G_O;  jb.bias[2] = bsum + 2 * HH; jb.C[2] = pre + 2 * CH; jb.sA[2] = KC; jb.sW[2] = KC;  jb.nk[2] = KC / BKH;  jb.start[2] = 512;
    jb.A[3] = xh;   jb.W[3] = wt16 + G_LX; jb.bias[3] = b_lx;          jb.C[3] = pre + 3 * CH; jb.sA[3] = KC; jb.sW[3] = KXP; jb.nk[3] = KXP / BKH; jb.start[3] = 768;
    jb.A[4] = ac16; jb.W[4] = wt16 + G_LC; jb.bias[4] = b_lc;          jb.C[4] = edge;         jb.sA[4] = HH; jb.sW[4] = HH;  jb.nk[4] = HH / BKH;  jb.start[4] = 1024;

    gemm_fp16<<<3072, 256, SMEM_BYTES>>>(jb, prefix);

    // ---- fused gates + ragged merge ----
    size_t CH4 = CH / 4;
    lattice_epilogue<<<(int)((CH4 + 255) / 256), 256>>>(pre, edge, allc,
                                                        prefix, numw,
                                                        (float*)d_out);
}